// round 3
// baseline (speedup 1.0000x reference)
#include <cuda_runtime.h>

#define NQ     18
#define NREPS  3
#define NBATCH 64
#define IDIM   32

__device__ __forceinline__ float2 cmul(float2 a, float2 b) {
    return make_float2(a.x * b.x - a.y * b.y, a.x * b.y + a.y * b.x);
}
__device__ __forceinline__ float2 cmulc(float2 a, float2 b) {   // a * conj(b)
    return make_float2(a.x * b.x + a.y * b.y, a.y * b.x - a.x * b.y);
}
__device__ __forceinline__ float2 cadd(float2 a, float2 b) {
    return make_float2(a.x + b.x, a.y + b.y);
}
__device__ __forceinline__ float2 csub(float2 a, float2 b) {
    return make_float2(a.x - b.x, a.y - b.y);
}

// One block per batch element. Exact MPS/transfer-matrix contraction:
//   - CNOT staircase == prefix-XOR basis permutation
//   - bond dimension exactly 8 = 2^REPS
//   - G_k[z] 8x8; left/right 8x8 density environments give all <Z_w>.
// Warp-row decomposition: each warp owns rows {2w, 2w+1}; the stage1->stage2
// handoff is warp-local (__syncwarp), one block barrier per site step.
// RY(a)RY(b)=RY(a+b) collapses all 2x2 products to 5 sincos per site.
__global__ __launch_bounds__(256, 1) void qenc_kernel(
    const float* __restrict__ xin,   // (64, 32)
    const float* __restrict__ vp,    // (3, 18, 2)
    float* __restrict__ out)         // (64, 18)
{
    const int b   = blockIdx.x;
    const int tid = threadIdx.x;

    __shared__ float2 G[NQ][2][8][9];     // padded (9) -> z-halves on disjoint banks
    __shared__ float2 rho[2][8][8];       // ping-pong left env
    __shared__ float2 sigR[NQ + 1][8][8]; // right envs (per-site, no race)
    __shared__ float2 Dm[NQ][8][8];       // signed per-site matrices
    __shared__ float2 tmpL[2][8][9];
    __shared__ float2 tmpR[2][8][9];
    __shared__ float  sc[NQ][5][2];       // (cos,sin) of: A1, A2B1, A3B2, B3, x
    __shared__ float  zred[NQ][8];

    // ---- setup: 5 sincos per site, one per thread (90 threads) ------------
    if (tid < NQ * 5) {
        const int k = tid / 5;
        const int g = tid - k * 5;
        float th;
        if (g == 0)      th = vp[(0 * NQ + k) * 2 + 0];
        else if (g == 1) th = vp[(1 * NQ + k) * 2 + 0] + vp[(0 * NQ + k) * 2 + 1];
        else if (g == 2) th = vp[(2 * NQ + k) * 2 + 0] + vp[(1 * NQ + k) * 2 + 1];
        else if (g == 3) th = vp[(2 * NQ + k) * 2 + 1];
        else             th = xin[b * IDIM + k];
        float s, c;
        __sincosf(0.5f * th, &s, &c);
        sc[k][g][0] = c;
        sc[k][g][1] = s;
    }
    // boundary env inits (independent threads)
    if (tid >= 192) {
        const int j = tid - 192;
        rho[0][j >> 3][j & 7] = make_float2(j == 0 ? 1.f : 0.f, 0.f);
    } else if (tid >= 128) {
        const int j = tid - 128;
        sigR[NQ][j >> 3][j & 7] = make_float2(1.f, 0.f);
    }
    __syncthreads();

    // ---- build G[k][z][p][n] ---------------------------------------------
    // G = R(B3)[z][n3] * R(A3B2)[n3^p3][n2] * R(A2B1)[n2^p2][n1] * w[n1^p1]
    // R(c,s) = [[c,-s],[s,c]];  w0 = (c1*cx, s1*sx),  w1 = (s1*cx, -c1*sx)
    #pragma unroll
    for (int ii = 0; ii < 9; ++ii) {
        const int idx = tid + ii * 256;
        const int k = idx >> 7;
        const int z = (idx >> 6) & 1;
        const int p = (idx >> 3) & 7;
        const int n = idx & 7;
        const int n1 = n & 1, n2 = (n >> 1) & 1, n3 = (n >> 2) & 1;
        const int p1 = p & 1, p2 = (p >> 1) & 1, p3 = (p >> 2) & 1;
        const float r3  = (z == n3) ? sc[k][3][0] : (z == 0 ? -sc[k][3][1] : sc[k][3][1]);
        const int   i3  = n3 ^ p3;
        const float rc3 = (i3 == n2) ? sc[k][2][0] : (i3 == 0 ? -sc[k][2][1] : sc[k][2][1]);
        const int   i2  = n2 ^ p2;
        const float rc2 = (i2 == n1) ? sc[k][1][0] : (i2 == 0 ? -sc[k][1][1] : sc[k][1][1]);
        const float coef = r3 * rc3 * rc2;
        const float c1 = sc[k][0][0], s1 = sc[k][0][1];
        const float cx = sc[k][4][0], sx = sc[k][4][1];
        float2 w;
        if ((n1 ^ p1) == 0) w = make_float2(c1 * cx,  s1 * sx);
        else                w = make_float2(s1 * cx, -c1 * sx);
        G[k][z][p][n] = make_float2(coef * w.x, coef * w.y);
    }
    __syncthreads();

    // ---- sweeps: warps 0-3 left (18 steps, emit Dm), warps 4-7 right (17) --
    const int half = tid >> 7;
    const int wip  = (tid >> 5) & 3;   // warp-in-half
    const int lane = tid & 31;
    const int z    = lane >> 4;
    const int il   = (lane >> 3) & 1;
    const int a    = lane & 7;         // stage1: output col; stage2: output col j
    const int i    = wip * 2 + il;     // owned row

    for (int t = 0; t < NQ; ++t) {
        if (half == 0) {
            // stage1: tmpL[z][i][a] = sum_m G[t][z][m][i] * rho[m][a]
            const float2* Gt = &G[t][z][0][0];       // row stride 9
            const float2* rr = &rho[t & 1][0][0];
            float2 acc0 = make_float2(0.f, 0.f);
            float2 acc1 = make_float2(0.f, 0.f);
            #pragma unroll
            for (int m = 0; m < 8; m += 2) {
                acc0 = cadd(acc0, cmul(Gt[m * 9 + i],       rr[m * 8 + a]));
                acc1 = cadd(acc1, cmul(Gt[(m + 1) * 9 + i], rr[(m + 1) * 8 + a]));
            }
            tmpL[z][i][a] = cadd(acc0, acc1);
            __syncwarp();
            // stage2: t_z[i][j] = sum_a2 tmpL[z][i][a2] * conj(G[t][z][a2][j])
            float2 s0 = make_float2(0.f, 0.f);
            float2 s1 = make_float2(0.f, 0.f);
            #pragma unroll
            for (int a2 = 0; a2 < 8; a2 += 2) {
                s0 = cadd(s0, cmulc(tmpL[z][i][a2],     G[t][z][a2][a]));
                s1 = cadd(s1, cmulc(tmpL[z][i][a2 + 1], G[t][z][a2 + 1][a]));
            }
            float2 t_me = cadd(s0, s1);
            float2 t_ot;
            t_ot.x = __shfl_xor_sync(0xffffffffu, t_me.x, 16);
            t_ot.y = __shfl_xor_sync(0xffffffffu, t_me.y, 16);
            if (z == 0) {
                if (t < NQ - 1) rho[(t + 1) & 1][i][a] = cadd(t_me, t_ot);
            } else {
                Dm[t][i][a] = csub(t_ot, t_me);   // t0 - t1
            }
        } else if (t < NQ - 1) {
            const int kR = NQ - 1 - t;
            // stage1: tmpR[z][i][a] = sum_m G[kR][z][i][m] * sigR[kR+1][m][a]
            const float2* Gk = &G[kR][z][0][0];
            const float2* ss = &sigR[kR + 1][0][0];
            float2 acc0 = make_float2(0.f, 0.f);
            float2 acc1 = make_float2(0.f, 0.f);
            #pragma unroll
            for (int m = 0; m < 8; m += 2) {
                acc0 = cadd(acc0, cmul(Gk[i * 9 + m],     ss[m * 8 + a]));
                acc1 = cadd(acc1, cmul(Gk[i * 9 + m + 1], ss[(m + 1) * 8 + a]));
            }
            tmpR[z][i][a] = cadd(acc0, acc1);
            __syncwarp();
            // stage2: t_z[i][j] = sum_a2 tmpR[z][i][a2] * conj(G[kR][z][j][a2])
            float2 s0 = make_float2(0.f, 0.f);
            float2 s1 = make_float2(0.f, 0.f);
            #pragma unroll
            for (int a2 = 0; a2 < 8; a2 += 2) {
                s0 = cadd(s0, cmulc(tmpR[z][i][a2],     G[kR][z][a][a2]));
                s1 = cadd(s1, cmulc(tmpR[z][i][a2 + 1], G[kR][z][a][a2 + 1]));
            }
            float2 t_me = cadd(s0, s1);
            float2 t_ot;
            t_ot.x = __shfl_xor_sync(0xffffffffu, t_me.x, 16);
            t_ot.y = __shfl_xor_sync(0xffffffffu, t_me.y, 16);
            if (z == 0) sigR[kR][i][a] = cadd(t_me, t_ot);
        }
        __syncthreads();
    }

    // ---- <Z_w> = Re( Dm[w] . sigma^(w+1) ) --------------------------------
    if (tid < NQ * 8) {
        const int w = tid >> 3;
        const int r = tid & 7;
        float acc = 0.f;
        #pragma unroll
        for (int j = 0; j < 8; ++j) {
            const float2 d = Dm[w][r][j];
            const float2 s = sigR[w + 1][r][j];
            acc += d.x * s.x - d.y * s.y;
        }
        zred[w][r] = acc;
    }
    __syncthreads();
    if (tid < NQ) {
        float sum = 0.f;
        #pragma unroll
        for (int j = 0; j < 8; ++j) sum += zred[tid][j];
        out[b * NQ + tid] = sum;
    }
}

extern "C" void kernel_launch(void* const* d_in, const int* in_sizes, int n_in,
                              void* d_out, int out_size)
{
    const float* x  = (const float*)d_in[0];   // input_vec (64,32)
    const float* vp = (const float*)d_in[1];   // var_params (3,18,2)
    if (n_in >= 2 && in_sizes[0] == NREPS * NQ * 2) {
        x  = (const float*)d_in[1];
        vp = (const float*)d_in[0];
    }
    qenc_kernel<<<NBATCH, 256>>>(x, vp, (float*)d_out);
}